// round 8
// baseline (speedup 1.0000x reference)
#include <cuda_runtime.h>
#include <cstdint>

#define B_   2
#define C_   32
#define T_   64
#define HW_  4096
#define N_   512
#define BN_  (B_*N_)         /* 1024 */
#define CH_  16
#define FT_  400
#define L_   (FT_*N_)        /* 204800 */
#define CNT_ (B_*L_)         /* 409600 */
#define OUT_OFF_RESULT ((size_t)B_*CH_*L_)  /* 6,553,600 */

// ---- scratch (device globals) ----
__device__ __align__(16) float g_r[B_*T_*HW_];            // 2 MB
// g_f: quad-plane layout. float4 plane p = t*4 + q, index [p][bn]
__device__ __align__(16) float g_f[(size_t)T_*4*BN_*4];   // 4 MB
__device__ __align__(16) float g_part[32*BN_];            // [col][block]
__device__ float g_ss[32];                                // sums[16] + sumsqs[16]
__device__ unsigned g_count = 0;

// ---- cp.async helpers ----
__device__ __forceinline__ void cp_async16(uint32_t dst, const void* src) {
    asm volatile("cp.async.ca.shared.global [%0], [%1], 16;" :: "r"(dst), "l"(src));
}
__device__ __forceinline__ void cp_commit() {
    asm volatile("cp.async.commit_group;");
}
template<int N> __device__ __forceinline__ void cp_wait() {
    asm volatile("cp.async.wait_group %0;" :: "n"(N));
}

// ---- compile-time lerp stat tables (fp32 ops identical to reference) ----
struct LerpTab { float wl[64]; float A[64]; float Bc[64]; float Cc[64]; };
constexpr LerpTab make_tab() {
    LerpTab tb{};
    const float step = (float)(63.0/399.0);
    for (int t = 0; t < FT_; t++) {
        float pos = (float)t * step;
        int i0 = (int)pos;
        int i1 = (i0 + 1 < T_) ? i0 + 1 : T_ - 1;
        float w = pos - (float)i0;
        float w0 = 1.0f - w;
        if (i1 == i0) {
            tb.wl[i0] += (w0 + w);
            tb.A[i0]  += (w0 + w) * (w0 + w);
        } else {
            tb.wl[i0] += w0;  tb.wl[i1] += w;
            tb.A[i0]  += w0 * w0;
            tb.Bc[i0] += 2.0f * w0 * w;
            tb.Cc[i0] += w * w;
        }
    }
    return tb;
}
__constant__ LerpTab c_tab = make_tab();

// ============================================================================
// k_r: r[b][t][hw] = Wr.x + br via cp.async double-buffer (MLP in smem).
// Block = (b,t,chunk of 512 hw). Each thread owns one float4 column; all its
// cp.async targets are self-read -> no syncthreads in the pipeline.
// ============================================================================
__global__ void __launch_bounds__(128) k_r(
    const float* __restrict__ x, const float* __restrict__ Wr,
    const float* __restrict__ br)
{
    __shared__ float buf[2][16][512];     // 32 KB
    __shared__ float w[32];
    if (threadIdx.x < 32) w[threadIdx.x] = Wr[threadIdx.x];
    __syncthreads();

    int bid = blockIdx.x;                 // 1024 = b(2) * t(64) * chunk(8)
    int chunk = bid & 7;
    int bt = bid >> 3;
    int b = bt >> 6, t = bt & 63;
    int col = threadIdx.x * 4;
    const float* base = x + ((size_t)(b*C_)*T_ + t)*HW_ + chunk*512 + col;
    uint32_t s0 = (uint32_t)__cvta_generic_to_shared(&buf[0][0][col]);
    uint32_t s1 = (uint32_t)__cvta_generic_to_shared(&buf[1][0][col]);

    // stage 0: channels 0..15
    #pragma unroll
    for (int c = 0; c < 16; c++)
        cp_async16(s0 + c*2048, base + (size_t)c*T_*HW_);
    cp_commit();
    // stage 1: channels 16..31
    #pragma unroll
    for (int c = 0; c < 16; c++)
        cp_async16(s1 + c*2048, base + (size_t)(16+c)*T_*HW_);
    cp_commit();

    float brv = br[0];
    float4 acc = make_float4(brv, brv, brv, brv);

    cp_wait<1>();                         // stage 0 landed (self-written)
    #pragma unroll
    for (int c = 0; c < 16; c++) {
        float4 v = *(const float4*)&buf[0][c][col];
        float wc = w[c];
        acc.x += wc*v.x; acc.y += wc*v.y; acc.z += wc*v.z; acc.w += wc*v.w;
    }
    cp_wait<0>();                         // stage 1 landed
    #pragma unroll
    for (int c = 0; c < 16; c++) {
        float4 v = *(const float4*)&buf[1][c][col];
        float wc = w[16+c];
        acc.x += wc*v.x; acc.y += wc*v.y; acc.z += wc*v.z; acc.w += wc*v.w;
    }
    *(float4*)&g_r[(size_t)bt*HW_ + chunk*512 + col] = acc;
}

// ============================================================================
// k_g: gather path (1024 blocks, one per (b,n)). Last block folds BN stats.
// ============================================================================
__global__ void __launch_bounds__(128, 8) k_g(
    const float* __restrict__ x, const int* __restrict__ coord,
    const float* __restrict__ W1, const float* __restrict__ Wf,
    const float* __restrict__ b1, const float* __restrict__ bf)
{
    __shared__ float xg[C_*T_];      // gather x [c][t] / Wf stage
    __shared__ float sWt[C_*CH_];    // folded weights [c][o]
    __shared__ float sbe[CH_];
    __shared__ float sf[T_*CH_];     // f [t][o] / W1 stage
    __shared__ float red_s[128];
    __shared__ float red_q[128];
    __shared__ float sbf[C_];
    __shared__ unsigned s_last;

    int bn = blockIdx.x;                   // 0..1023
    int tid = threadIdx.x;
    int b = bn >> 9;
    int idx = coord[bn*2]*64 + coord[bn*2+1];

    // issue 16 scattered x loads early (max MLP)
    const float* xp = x + (size_t)b*C_*T_*HW_ + idx;
    float rv[16];
    #pragma unroll
    for (int i = 0; i < 16; i++)
        rv[i] = xp[(size_t)(tid + i*128) * HW_];

    // stage W1 -> sf, Wf -> xg, bf -> sbf
    for (int e = tid; e < CH_*C_; e += 128) sf[e] = W1[e];
    for (int e = tid; e < C_*C_; e += 128) xg[e] = Wf[e];
    if (tid < 32) sbf[tid] = bf[tid];
    __syncthreads();

    // fold: sWt[c][o] = sum_k W1[o][k] * Wf[k][c]
    #pragma unroll
    for (int i = 0; i < 4; i++) {
        int e = tid*4 + i;
        int c = e >> 4, o = e & 15;
        float a = 0.f;
        #pragma unroll
        for (int k = 0; k < 32; k++) a += sf[o*32+k] * xg[k*32 + c];
        sWt[c*CH_+o] = a;
    }
    if (tid < CH_) {
        float bb = b1[tid];
        #pragma unroll
        for (int k = 0; k < 32; k++) bb += sf[tid*32+k] * sbf[k];
        sbe[tid] = bb;
    }
    __syncthreads();
    #pragma unroll
    for (int i = 0; i < 16; i++) xg[tid + i*128] = rv[i];   // park x [c][t]
    __syncthreads();

    // f[t][o] = beff[o] + sum_c Wt[c][o] * xg[c][t]
    #pragma unroll
    for (int i = 0; i < 8; i++) {
        int e = tid + i*128;
        int t = e >> 4, o = e & 15;
        float a = sbe[o];
        #pragma unroll
        for (int c = 0; c < 32; c++) a += sWt[c*CH_+o] * xg[c*64+t];
        sf[e] = a;
    }
    __syncthreads();

    // store f -> g_f quad-plane layout: plane p = t*4+q, slot bn
    {
        float4* gf4 = (float4*)g_f;
        const float4* sf4 = (const float4*)sf;
        #pragma unroll
        for (int i = 0; i < 2; i++) {
            int e4 = tid + i*128;            // e4 = t*4 + q
            gf4[(size_t)e4*BN_ + bn] = sf4[e4];
        }
    }

    // table-based stats
    {
        int o = tid & 15, j = tid >> 4;
        float s_acc = 0.f, q_acc = 0.f;
        #pragma unroll
        for (int k = 0; k < 8; k++) {
            int i  = j + k*8;
            int i1 = (i < 63) ? i + 1 : 63;
            float fi  = sf[i*16 + o];
            float fi1 = sf[i1*16 + o];
            s_acc += c_tab.wl[i] * fi;
            q_acc += c_tab.A[i]*fi*fi + c_tab.Bc[i]*fi*fi1 + c_tab.Cc[i]*fi1*fi1;
        }
        red_s[j*16 + o] = s_acc;
        red_q[j*16 + o] = q_acc;
    }
    __syncthreads();
    if (tid < 32) {
        int c = tid & 15;
        const float* src = (tid < 16) ? red_s : red_q;
        float tot = 0.f;
        #pragma unroll
        for (int jj = 0; jj < 8; jj++) tot += src[jj*16 + c];
        g_part[tid*BN_ + bn] = tot;
    }

    // last block folds g_part -> g_ss
    __threadfence();
    if (tid == 0) s_last = (atomicAdd(&g_count, 1u) == 1023u) ? 1u : 0u;
    __syncthreads();
    if (s_last) {
        int c = tid >> 2, qd = tid & 3;
        const float4* p = (const float4*)(g_part + c*BN_) + qd*64;
        float acc = 0.f;
        #pragma unroll 16
        for (int k = 0; k < 64; k++) {
            float4 v4 = p[k];
            acc += (v4.x + v4.y) + (v4.z + v4.w);
        }
        red_s[tid] = acc;
        __syncthreads();
        if (tid < 32) {
            g_ss[tid] = (red_s[tid*4] + red_s[tid*4+1])
                      + (red_s[tid*4+2] + red_s[tid*4+3]);
            if (tid == 0) g_count = 0;   // reset for next graph replay
        }
    }
}

// ============================================================================
// k_fin: blocks [0,3200) -> result lerp; blocks [3200,4800) -> BN+ReLU+W2
// ============================================================================
__global__ void __launch_bounds__(256) k_fin(
    const float* __restrict__ gamma, const float* __restrict__ beta,
    const float* __restrict__ W2, const float* __restrict__ b2,
    float* __restrict__ out)
{
    __shared__ float sW2[CH_*CH_], sb2[CH_], ssc[CH_], ssh[CH_];

    if (blockIdx.x < 3200) {
        int tid = blockIdx.x*256 + threadIdx.x;      // 819200
        int hw4 = tid & 1023;
        int bt  = tid >> 10;
        int t = bt % FT_;
        int b = bt / FT_;
        const float step = (float)(63.0/399.0);
        float pos = (float)t * step;
        int i0 = (int)pos;
        int i1 = min(i0+1, T_-1);
        float w = pos - (float)i0, w0 = 1.f - w;
        float4 a = ((const float4*)(g_r + (b*T_+i0)*HW_))[hw4];
        float4 c = ((const float4*)(g_r + (b*T_+i1)*HW_))[hw4];
        float4 v = make_float4(a.x*w0 + c.x*w, a.y*w0 + c.y*w,
                               a.z*w0 + c.z*w, a.w*w0 + c.w*w);
        ((float4*)(out + OUT_OFF_RESULT))[tid] = v;
        return;
    }

    if (threadIdx.x < CH_*CH_) sW2[threadIdx.x] = W2[threadIdx.x];
    if (threadIdx.x < CH_) {
        int o = threadIdx.x;
        sb2[o] = b2[o];
        float mean = g_ss[o]    * (1.f/(float)CNT_);
        float var  = g_ss[o+16] * (1.f/(float)CNT_) - mean*mean;
        float sc = gamma[o] * rsqrtf(var + 1e-5f);
        ssc[o] = sc;
        ssh[o] = beta[o] - mean*sc;
    }
    __syncthreads();
    int tid = (blockIdx.x - 3200)*256 + threadIdx.x;  // 409600
    int b = tid / L_;
    int l = tid - b*L_;
    int t = l >> 9, n = l & (N_-1);
    int bn = b*N_ + n;
    const float step = (float)(63.0/399.0);
    float pos = (float)t * step;
    int i0 = (int)pos;
    int i1 = min(i0+1, T_-1);
    float w = pos - (float)i0, w0 = 1.f - w;
    const float4* gf4 = (const float4*)g_f;
    float4 a0 = gf4[(size_t)(i0*4+0)*BN_ + bn];
    float4 a1 = gf4[(size_t)(i0*4+1)*BN_ + bn];
    float4 a2 = gf4[(size_t)(i0*4+2)*BN_ + bn];
    float4 a3 = gf4[(size_t)(i0*4+3)*BN_ + bn];
    float4 c0 = gf4[(size_t)(i1*4+0)*BN_ + bn];
    float4 c1 = gf4[(size_t)(i1*4+1)*BN_ + bn];
    float4 c2 = gf4[(size_t)(i1*4+2)*BN_ + bn];
    float4 c3 = gf4[(size_t)(i1*4+3)*BN_ + bn];
    float hr[CH_];
    hr[0]=a0.x*w0+c0.x*w; hr[1]=a0.y*w0+c0.y*w; hr[2]=a0.z*w0+c0.z*w; hr[3]=a0.w*w0+c0.w*w;
    hr[4]=a1.x*w0+c1.x*w; hr[5]=a1.y*w0+c1.y*w; hr[6]=a1.z*w0+c1.z*w; hr[7]=a1.w*w0+c1.w*w;
    hr[8]=a2.x*w0+c2.x*w; hr[9]=a2.y*w0+c2.y*w; hr[10]=a2.z*w0+c2.z*w; hr[11]=a2.w*w0+c2.w*w;
    hr[12]=a3.x*w0+c3.x*w; hr[13]=a3.y*w0+c3.y*w; hr[14]=a3.z*w0+c3.z*w; hr[15]=a3.w*w0+c3.w*w;
    #pragma unroll
    for (int o = 0; o < CH_; o++) hr[o] = fmaxf(ssc[o]*hr[o] + ssh[o], 0.f);
    #pragma unroll
    for (int o2 = 0; o2 < CH_; o2++) {
        float acc = sb2[o2];
        #pragma unroll
        for (int o = 0; o < CH_; o++) acc += sW2[o2*16+o] * hr[o];
        out[((size_t)(b*CH_+o2))*L_ + l] = acc;
    }
}

extern "C" void kernel_launch(void* const* d_in, const int* in_sizes, int n_in,
                              void* d_out, int out_size) {
    const float* x     = (const float*)d_in[0];
    const int*   coord = (const int*)  d_in[1];
    const float* Wf    = (const float*)d_in[2];
    const float* bf    = (const float*)d_in[3];
    const float* Wr    = (const float*)d_in[4];
    const float* br    = (const float*)d_in[5];
    const float* W1    = (const float*)d_in[6];
    const float* b1    = (const float*)d_in[7];
    const float* gamma = (const float*)d_in[8];
    const float* beta  = (const float*)d_in[9];
    const float* W2    = (const float*)d_in[10];
    const float* b2    = (const float*)d_in[11];
    float* out = (float*)d_out;

    static cudaStream_t s2 = nullptr;
    static cudaEvent_t eFork = nullptr, eJoin = nullptr;
    if (!s2) {
        cudaStreamCreateWithFlags(&s2, cudaStreamNonBlocking);
        cudaEventCreateWithFlags(&eFork, cudaEventDisableTiming);
        cudaEventCreateWithFlags(&eJoin, cudaEventDisableTiming);
    }

    // fork: k_r (x stream) on side stream, k_g (gather) on main — independent
    cudaEventRecord(eFork, 0);
    cudaStreamWaitEvent(s2, eFork, 0);
    k_r<<<1024, 128, 0, s2>>>(x, Wr, br);
    cudaEventRecord(eJoin, s2);

    k_g<<<1024, 128>>>(x, coord, W1, Wf, b1, bf);

    cudaStreamWaitEvent(0, eJoin, 0);
    k_fin<<<4800, 256>>>(gamma, beta, W2, b2, out);
}

// round 9
// speedup vs baseline: 1.1168x; 1.1168x over previous
#include <cuda_runtime.h>
#include <cstdint>

#define B_   2
#define C_   32
#define T_   64
#define HW_  4096
#define N_   512
#define BN_  (B_*N_)         /* 1024 */
#define CH_  16
#define FT_  400
#define L_   (FT_*N_)        /* 204800 */
#define CNT_ (B_*L_)         /* 409600 */
#define OUT_OFF_RESULT ((size_t)B_*CH_*L_)  /* 6,553,600 */

// ---- scratch (device globals) ----
__device__ __align__(16) float g_r[B_*T_*HW_];            // 2 MB
// g_f: quad-plane layout. float4 plane p = t*4 + q, index [p][bn]
__device__ __align__(16) float g_f[(size_t)T_*4*BN_*4];   // 4 MB
__device__ __align__(16) float g_part[32*BN_];            // [col][block]
__device__ float g_ss[32];                                // sums[16] + sumsqs[16]
__device__ unsigned g_count = 0;

// ---- cp.async helpers ----
__device__ __forceinline__ void cp_async16(uint32_t dst, const void* src) {
    asm volatile("cp.async.ca.shared.global [%0], [%1], 16;" :: "r"(dst), "l"(src));
}
__device__ __forceinline__ void cp_commit() {
    asm volatile("cp.async.commit_group;");
}
template<int N> __device__ __forceinline__ void cp_wait() {
    asm volatile("cp.async.wait_group %0;" :: "n"(N));
}

// ---- compile-time lerp stat tables (fp32 ops identical to reference) ----
struct LerpTab { float wl[64]; float A[64]; float Bc[64]; float Cc[64]; };
constexpr LerpTab make_tab() {
    LerpTab tb{};
    const float step = (float)(63.0/399.0);
    for (int t = 0; t < FT_; t++) {
        float pos = (float)t * step;
        int i0 = (int)pos;
        int i1 = (i0 + 1 < T_) ? i0 + 1 : T_ - 1;
        float w = pos - (float)i0;
        float w0 = 1.0f - w;
        if (i1 == i0) {
            tb.wl[i0] += (w0 + w);
            tb.A[i0]  += (w0 + w) * (w0 + w);
        } else {
            tb.wl[i0] += w0;  tb.wl[i1] += w;
            tb.A[i0]  += w0 * w0;
            tb.Bc[i0] += 2.0f * w0 * w;
            tb.Cc[i0] += w * w;
        }
    }
    return tb;
}
__constant__ LerpTab c_tab = make_tab();

// ============================================================================
// k_r: r[b][t][hw] = Wr.x + br via cp.async double-buffer. Streams ALL of x
// through L2 (x stays resident: 67 MB < 126 MB), warming it for k_g.
// ============================================================================
__global__ void __launch_bounds__(128) k_r(
    const float* __restrict__ x, const float* __restrict__ Wr,
    const float* __restrict__ br)
{
    __shared__ float buf[2][16][512];     // 32 KB
    __shared__ float w[32];
    if (threadIdx.x < 32) w[threadIdx.x] = Wr[threadIdx.x];
    __syncthreads();

    int bid = blockIdx.x;                 // 1024 = b(2) * t(64) * chunk(8)
    int chunk = bid & 7;
    int bt = bid >> 3;
    int b = bt >> 6, t = bt & 63;
    int col = threadIdx.x * 4;
    const float* base = x + ((size_t)(b*C_)*T_ + t)*HW_ + chunk*512 + col;
    uint32_t s0 = (uint32_t)__cvta_generic_to_shared(&buf[0][0][col]);
    uint32_t s1 = (uint32_t)__cvta_generic_to_shared(&buf[1][0][col]);

    #pragma unroll
    for (int c = 0; c < 16; c++)
        cp_async16(s0 + c*2048, base + (size_t)c*T_*HW_);
    cp_commit();
    #pragma unroll
    for (int c = 0; c < 16; c++)
        cp_async16(s1 + c*2048, base + (size_t)(16+c)*T_*HW_);
    cp_commit();

    float brv = br[0];
    float4 acc = make_float4(brv, brv, brv, brv);

    cp_wait<1>();
    #pragma unroll
    for (int c = 0; c < 16; c++) {
        float4 v = *(const float4*)&buf[0][c][col];
        float wc = w[c];
        acc.x += wc*v.x; acc.y += wc*v.y; acc.z += wc*v.z; acc.w += wc*v.w;
    }
    cp_wait<0>();
    #pragma unroll
    for (int c = 0; c < 16; c++) {
        float4 v = *(const float4*)&buf[1][c][col];
        float wc = w[16+c];
        acc.x += wc*v.x; acc.y += wc*v.y; acc.z += wc*v.z; acc.w += wc*v.w;
    }
    *(float4*)&g_r[(size_t)bt*HW_ + chunk*512 + col] = acc;
}

// ============================================================================
// k_g: gather path (1024 blocks, one per (b,n)). Runs AFTER k_r so the 2M
// scattered x reads hit L2. Last block folds BN stats.
// ============================================================================
__global__ void __launch_bounds__(128, 8) k_g(
    const float* __restrict__ x, const int* __restrict__ coord,
    const float* __restrict__ W1, const float* __restrict__ Wf,
    const float* __restrict__ b1, const float* __restrict__ bf)
{
    __shared__ float xg[C_*T_];      // gather x [c][t] / Wf stage
    __shared__ float sWt[C_*CH_];    // folded weights [c][o]
    __shared__ float sbe[CH_];
    __shared__ float sf[T_*CH_];     // f [t][o] / W1 stage
    __shared__ float red_s[128];
    __shared__ float red_q[128];
    __shared__ float sbf[C_];
    __shared__ unsigned s_last;

    int bn = blockIdx.x;                   // 0..1023
    int tid = threadIdx.x;
    int b = bn >> 9;
    int idx = coord[bn*2]*64 + coord[bn*2+1];

    // 16 scattered x loads, issued up-front (L2 hits after k_r)
    const float* xp = x + (size_t)b*C_*T_*HW_ + idx;
    float rv[16];
    #pragma unroll
    for (int i = 0; i < 16; i++)
        rv[i] = xp[(size_t)(tid + i*128) * HW_];

    // stage W1 -> sf, Wf -> xg, bf -> sbf
    for (int e = tid; e < CH_*C_; e += 128) sf[e] = W1[e];
    for (int e = tid; e < C_*C_; e += 128) xg[e] = Wf[e];
    if (tid < 32) sbf[tid] = bf[tid];
    __syncthreads();

    // fold: sWt[c][o] = sum_k W1[o][k] * Wf[k][c]
    #pragma unroll
    for (int i = 0; i < 4; i++) {
        int e = tid*4 + i;
        int c = e >> 4, o = e & 15;
        float a = 0.f;
        #pragma unroll
        for (int k = 0; k < 32; k++) a += sf[o*32+k] * xg[k*32 + c];
        sWt[c*CH_+o] = a;
    }
    if (tid < CH_) {
        float bb = b1[tid];
        #pragma unroll
        for (int k = 0; k < 32; k++) bb += sf[tid*32+k] * sbf[k];
        sbe[tid] = bb;
    }
    __syncthreads();
    #pragma unroll
    for (int i = 0; i < 16; i++) xg[tid + i*128] = rv[i];   // park x [c][t]
    __syncthreads();

    // f[t][o] = beff[o] + sum_c Wt[c][o] * xg[c][t]
    #pragma unroll
    for (int i = 0; i < 8; i++) {
        int e = tid + i*128;
        int t = e >> 4, o = e & 15;
        float a = sbe[o];
        #pragma unroll
        for (int c = 0; c < 32; c++) a += sWt[c*CH_+o] * xg[c*64+t];
        sf[e] = a;
    }
    __syncthreads();

    // store f -> g_f quad-plane layout
    {
        float4* gf4 = (float4*)g_f;
        const float4* sf4 = (const float4*)sf;
        #pragma unroll
        for (int i = 0; i < 2; i++) {
            int e4 = tid + i*128;            // e4 = t*4 + q
            gf4[(size_t)e4*BN_ + bn] = sf4[e4];
        }
    }

    // table-based stats
    {
        int o = tid & 15, j = tid >> 4;
        float s_acc = 0.f, q_acc = 0.f;
        #pragma unroll
        for (int k = 0; k < 8; k++) {
            int i  = j + k*8;
            int i1 = (i < 63) ? i + 1 : 63;
            float fi  = sf[i*16 + o];
            float fi1 = sf[i1*16 + o];
            s_acc += c_tab.wl[i] * fi;
            q_acc += c_tab.A[i]*fi*fi + c_tab.Bc[i]*fi*fi1 + c_tab.Cc[i]*fi1*fi1;
        }
        red_s[j*16 + o] = s_acc;
        red_q[j*16 + o] = q_acc;
    }
    __syncthreads();
    if (tid < 32) {
        int c = tid & 15;
        const float* src = (tid < 16) ? red_s : red_q;
        float tot = 0.f;
        #pragma unroll
        for (int jj = 0; jj < 8; jj++) tot += src[jj*16 + c];
        g_part[tid*BN_ + bn] = tot;
    }

    // last block folds g_part -> g_ss
    __threadfence();
    if (tid == 0) s_last = (atomicAdd(&g_count, 1u) == 1023u) ? 1u : 0u;
    __syncthreads();
    if (s_last) {
        int c = tid >> 2, qd = tid & 3;
        const float4* p = (const float4*)(g_part + c*BN_) + qd*64;
        float acc = 0.f;
        #pragma unroll 16
        for (int k = 0; k < 64; k++) {
            float4 v4 = p[k];
            acc += (v4.x + v4.y) + (v4.z + v4.w);
        }
        red_s[tid] = acc;
        __syncthreads();
        if (tid < 32) {
            g_ss[tid] = (red_s[tid*4] + red_s[tid*4+1])
                      + (red_s[tid*4+2] + red_s[tid*4+3]);
            if (tid == 0) g_count = 0;   // reset for next graph replay
        }
    }
}

// ============================================================================
// k_fin: blocks [0,3200) -> result lerp; blocks [3200,4800) -> BN+ReLU+W2
// ============================================================================
__global__ void __launch_bounds__(256) k_fin(
    const float* __restrict__ gamma, const float* __restrict__ beta,
    const float* __restrict__ W2, const float* __restrict__ b2,
    float* __restrict__ out)
{
    __shared__ float sW2[CH_*CH_], sb2[CH_], ssc[CH_], ssh[CH_];

    if (blockIdx.x < 3200) {
        int tid = blockIdx.x*256 + threadIdx.x;      // 819200
        int hw4 = tid & 1023;
        int bt  = tid >> 10;
        int t = bt % FT_;
        int b = bt / FT_;
        const float step = (float)(63.0/399.0);
        float pos = (float)t * step;
        int i0 = (int)pos;
        int i1 = min(i0+1, T_-1);
        float w = pos - (float)i0, w0 = 1.f - w;
        float4 a = ((const float4*)(g_r + (b*T_+i0)*HW_))[hw4];
        float4 c = ((const float4*)(g_r + (b*T_+i1)*HW_))[hw4];
        float4 v = make_float4(a.x*w0 + c.x*w, a.y*w0 + c.y*w,
                               a.z*w0 + c.z*w, a.w*w0 + c.w*w);
        ((float4*)(out + OUT_OFF_RESULT))[tid] = v;
        return;
    }

    if (threadIdx.x < CH_*CH_) sW2[threadIdx.x] = W2[threadIdx.x];
    if (threadIdx.x < CH_) {
        int o = threadIdx.x;
        sb2[o] = b2[o];
        float mean = g_ss[o]    * (1.f/(float)CNT_);
        float var  = g_ss[o+16] * (1.f/(float)CNT_) - mean*mean;
        float sc = gamma[o] * rsqrtf(var + 1e-5f);
        ssc[o] = sc;
        ssh[o] = beta[o] - mean*sc;
    }
    __syncthreads();
    int tid = (blockIdx.x - 3200)*256 + threadIdx.x;  // 409600
    int b = tid / L_;
    int l = tid - b*L_;
    int t = l >> 9, n = l & (N_-1);
    int bn = b*N_ + n;
    const float step = (float)(63.0/399.0);
    float pos = (float)t * step;
    int i0 = (int)pos;
    int i1 = min(i0+1, T_-1);
    float w = pos - (float)i0, w0 = 1.f - w;
    const float4* gf4 = (const float4*)g_f;
    float4 a0 = gf4[(size_t)(i0*4+0)*BN_ + bn];
    float4 a1 = gf4[(size_t)(i0*4+1)*BN_ + bn];
    float4 a2 = gf4[(size_t)(i0*4+2)*BN_ + bn];
    float4 a3 = gf4[(size_t)(i0*4+3)*BN_ + bn];
    float4 c0 = gf4[(size_t)(i1*4+0)*BN_ + bn];
    float4 c1 = gf4[(size_t)(i1*4+1)*BN_ + bn];
    float4 c2 = gf4[(size_t)(i1*4+2)*BN_ + bn];
    float4 c3 = gf4[(size_t)(i1*4+3)*BN_ + bn];
    float hr[CH_];
    hr[0]=a0.x*w0+c0.x*w; hr[1]=a0.y*w0+c0.y*w; hr[2]=a0.z*w0+c0.z*w; hr[3]=a0.w*w0+c0.w*w;
    hr[4]=a1.x*w0+c1.x*w; hr[5]=a1.y*w0+c1.y*w; hr[6]=a1.z*w0+c1.z*w; hr[7]=a1.w*w0+c1.w*w;
    hr[8]=a2.x*w0+c2.x*w; hr[9]=a2.y*w0+c2.y*w; hr[10]=a2.z*w0+c2.z*w; hr[11]=a2.w*w0+c2.w*w;
    hr[12]=a3.x*w0+c3.x*w; hr[13]=a3.y*w0+c3.y*w; hr[14]=a3.z*w0+c3.z*w; hr[15]=a3.w*w0+c3.w*w;
    #pragma unroll
    for (int o = 0; o < CH_; o++) hr[o] = fmaxf(ssc[o]*hr[o] + ssh[o], 0.f);
    #pragma unroll
    for (int o2 = 0; o2 < CH_; o2++) {
        float acc = sb2[o2];
        #pragma unroll
        for (int o = 0; o < CH_; o++) acc += sW2[o2*16+o] * hr[o];
        out[((size_t)(b*CH_+o2))*L_ + l] = acc;
    }
}

extern "C" void kernel_launch(void* const* d_in, const int* in_sizes, int n_in,
                              void* d_out, int out_size) {
    const float* x     = (const float*)d_in[0];
    const int*   coord = (const int*)  d_in[1];
    const float* Wf    = (const float*)d_in[2];
    const float* bf    = (const float*)d_in[3];
    const float* Wr    = (const float*)d_in[4];
    const float* br    = (const float*)d_in[5];
    const float* W1    = (const float*)d_in[6];
    const float* b1    = (const float*)d_in[7];
    const float* gamma = (const float*)d_in[8];
    const float* beta  = (const float*)d_in[9];
    const float* W2    = (const float*)d_in[10];
    const float* b2    = (const float*)d_in[11];
    float* out = (float*)d_out;

    k_r  <<<1024, 128>>>(x, Wr, br);             // streams x -> L2 warm
    k_g  <<<1024, 128>>>(x, coord, W1, Wf, b1, bf); // scattered reads = L2 hits
    k_fin<<<4800, 256>>>(gamma, beta, W2, b2, out);
}